// round 15
// baseline (speedup 1.0000x reference)
#include <cuda_runtime.h>
#include <math.h>
#include <stdint.h>

// ---------------- problem constants ----------------
#define BB   64
#define DM   512
#define NH   8
#define DKH  64
#define DI   2048
#define NLAY 4
#define SS   12
#define REP_IDX 1
#define LMAX 385

// ---------------- scratch ----------------
__device__ int   g_seq_len[BB];
__device__ int   g_poi_idx[BB * LMAX];
__device__ int   g_tok_idx[BB * LMAX];
__device__ float g_x [BB * LMAX * DM];
__device__ float g_q [BB * LMAX * DM];
__device__ float g_k [BB * LMAX * DM];
__device__ float g_v [BB * LMAX * DM];
__device__ float g_ao[BB * LMAX * DM];
__device__ float g_y [BB * LMAX * DM];
__device__ float g_h [BB * LMAX * DI];
__device__ float g_pt[SS * DM];
// tf32-rounded weights
__device__ float g_wq[NLAY * DM * DM];
__device__ float g_wk[NLAY * DM * DM];
__device__ float g_wv[NLAY * DM * DM];
__device__ float g_wo[NLAY * DM * DM];
__device__ float g_w1[NLAY * DM * DI];
__device__ float g_w2[NLAY * DI * DM];

// ---------------- tf32 helpers ----------------
__device__ __forceinline__ float f2tf(float x) {
    uint32_t u;
    asm("cvt.rna.tf32.f32 %0, %1;" : "=r"(u) : "f"(x));
    return __uint_as_float(u);
}
__device__ __forceinline__ float4 f2tf4(float4 a) {
    return make_float4(f2tf(a.x), f2tf(a.y), f2tf(a.z), f2tf(a.w));
}

// ---------------- fused weight rounding ----------------
#define NA (NLAY * DM * DM / 4)
#define NB (NLAY * DM * DI / 4)
__global__ void round_all_kernel(
    const float4* __restrict__ wq, const float4* __restrict__ wk,
    const float4* __restrict__ wv, const float4* __restrict__ wo,
    const float4* __restrict__ w1, const float4* __restrict__ w2,
    float4* __restrict__ dq, float4* __restrict__ dk,
    float4* __restrict__ dv, float4* __restrict__ doo,
    float4* __restrict__ d1, float4* __restrict__ d2) {
    const int total = 4 * NA + 2 * NB;
    int stride = gridDim.x * blockDim.x;
    for (int i = blockIdx.x * blockDim.x + threadIdx.x; i < total; i += stride) {
        const float4* s; float4* d; int off;
        if      (i <     NA)      { s = wq; d = dq;  off = i; }
        else if (i < 2 * NA)      { s = wk; d = dk;  off = i - NA; }
        else if (i < 3 * NA)      { s = wv; d = dv;  off = i - 2 * NA; }
        else if (i < 4 * NA)      { s = wo; d = doo; off = i - 3 * NA; }
        else if (i < 4 * NA + NB) { s = w1; d = d1;  off = i - 4 * NA; }
        else                      { s = w2; d = d2;  off = i - 4 * NA - NB; }
        d[off] = f2tf4(s[off]);
    }
}

// ---------------- sinusoid table ----------------
__global__ void postab_kernel() {
    int t = blockIdx.x;
    for (int d = threadIdx.x; d < DM; d += blockDim.x) {
        int i2 = d & ~1;
        float f = powf(10000.0f, -(float)i2 / (float)DM);
        float ang = (float)t * f;
        g_pt[t * DM + d] = (d & 1) ? cosf(ang) : sinf(ang);
    }
}

// ---------------- pack ----------------
__global__ void pack_kernel(const int* __restrict__ npl,
                            const int* __restrict__ ttn, int L) {
    int b = threadIdx.x;
    if (b >= BB) return;
    int start = 0;
    for (int i = 0; i < b; i++) start += npl[i];
    int end = start + npl[b];
    int pos = 1;
    for (int p = start; p < end; p++) {
        int t = ttn[p];
        for (int u = 0; u < t && pos < L; u++) {
            g_poi_idx[b * L + pos] = p;
            g_tok_idx[b * L + pos] = u;
            pos++;
        }
    }
    g_seq_len[b] = pos;
}

// ---------------- block reduce (128 threads) ----------------
__device__ __forceinline__ void block_reduce2_128(float& s, float& sq) {
    #pragma unroll
    for (int o = 16; o > 0; o >>= 1) {
        s  += __shfl_xor_sync(0xFFFFFFFFu, s,  o);
        sq += __shfl_xor_sync(0xFFFFFFFFu, sq, o);
    }
    __shared__ float rs[4], rq[4];
    int w = threadIdx.x >> 5, ln = threadIdx.x & 31;
    if (ln == 0) { rs[w] = s; rq[w] = sq; }
    __syncthreads();
    s  = rs[0] + rs[1] + rs[2] + rs[3];
    sq = rq[0] + rq[1] + rq[2] + rq[3];
}

// ---------------- embed + final LN ----------------
__global__ __launch_bounds__(128) void embed_ln_kernel(
    const int* __restrict__ poi_type, const float* __restrict__ loc_emb,
    const float* __restrict__ emb, const float* __restrict__ lnf_g,
    const float* __restrict__ lnf_b, int L) {
    int row = blockIdx.x;
    int b = row / L, l = row - b * L;
    int tid = threadIdx.x;
    int d0 = tid * 4;
    float v[4];
    int sl = g_seq_len[b];
    if (l == 0) {
        #pragma unroll
        for (int i = 0; i < 4; i++) v[i] = emb[REP_IDX * DM + d0 + i];
    } else if (l < sl) {
        int p = g_poi_idx[b * L + l];
        int t = g_tok_idx[b * L + l];
        int tok = poi_type[p * SS + t];
        float4 ev = *(const float4*)(emb + (size_t)tok * DM + d0);
        float4 pv = *(const float4*)(g_pt + t * DM + d0);
        float4 lv = *(const float4*)(loc_emb + (size_t)p * DM + d0);
        v[0] = ev.x + pv.x + lv.x;
        v[1] = ev.y + pv.y + lv.y;
        v[2] = ev.z + pv.z + lv.z;
        v[3] = ev.w + pv.w + lv.w;
    } else {
        #pragma unroll
        for (int i = 0; i < 4; i++) v[i] = 0.0f;
    }
    float s = v[0] + v[1] + v[2] + v[3];
    float sq = v[0]*v[0] + v[1]*v[1] + v[2]*v[2] + v[3]*v[3];
    block_reduce2_128(s, sq);
    float mean = s * (1.0f / DM);
    float var  = sq * (1.0f / DM) - mean * mean;
    float r = rsqrtf(var + 1e-6f);
    float4 o;
    o.x = f2tf(lnf_g[d0+0] * (v[0]-mean) * r + lnf_b[d0+0]);
    o.y = f2tf(lnf_g[d0+1] * (v[1]-mean) * r + lnf_b[d0+1]);
    o.z = f2tf(lnf_g[d0+2] * (v[2]-mean) * r + lnf_b[d0+2]);
    o.w = f2tf(lnf_g[d0+3] * (v[3]-mean) * r + lnf_b[d0+3]);
    *(float4*)(g_x + (size_t)row * DM + d0) = o;
}

// ---------------- residual + LN: warp per row ----------------
__global__ __launch_bounds__(256) void resid_ln_kernel(
    const float* __restrict__ x, const float* __restrict__ y,
    const float* __restrict__ g, const float* __restrict__ bb,
    float* __restrict__ dst, int do_round, int M) {
    int row = blockIdx.x * 8 + (threadIdx.x >> 5);
    if (row >= M) return;
    int lane = threadIdx.x & 31;
    size_t base = (size_t)row * DM + lane * 4;
    float4 a[4];
    float s = 0.f, sq = 0.f;
    #pragma unroll
    for (int j = 0; j < 4; j++) {
        float4 xv = *(const float4*)(x + base + j * 128);
        float4 yv = *(const float4*)(y + base + j * 128);
        float4 t = make_float4(xv.x+yv.x, xv.y+yv.y, xv.z+yv.z, xv.w+yv.w);
        a[j] = t;
        s  += t.x + t.y + t.z + t.w;
        sq += t.x*t.x + t.y*t.y + t.z*t.z + t.w*t.w;
    }
    #pragma unroll
    for (int o = 16; o > 0; o >>= 1) {
        s  += __shfl_xor_sync(0xFFFFFFFFu, s,  o);
        sq += __shfl_xor_sync(0xFFFFFFFFu, sq, o);
    }
    float mean = s * (1.0f / DM);
    float var  = sq * (1.0f / DM) - mean * mean;
    float r = rsqrtf(var + 1e-6f);
    #pragma unroll
    for (int j = 0; j < 4; j++) {
        int d0 = lane * 4 + j * 128;
        float4 o;
        o.x = g[d0+0] * (a[j].x - mean) * r + bb[d0+0];
        o.y = g[d0+1] * (a[j].y - mean) * r + bb[d0+1];
        o.z = g[d0+2] * (a[j].z - mean) * r + bb[d0+2];
        o.w = g[d0+3] * (a[j].w - mean) * r + bb[d0+3];
        if (do_round) o = f2tf4(o);
        *(float4*)(dst + base + j * 128) = o;
    }
}

// ---------------- mma helper ----------------
__device__ __forceinline__ void mma1688(float* c, const uint32_t* a, const uint32_t* b) {
    asm volatile(
        "mma.sync.aligned.m16n8k8.row.col.f32.tf32.tf32.f32 "
        "{%0,%1,%2,%3}, {%4,%5,%6,%7}, {%8,%9}, {%0,%1,%2,%3};"
        : "+f"(c[0]), "+f"(c[1]), "+f"(c[2]), "+f"(c[3])
        : "r"(a[0]), "r"(a[1]), "r"(a[2]), "r"(a[3]),
          "r"(b[0]), "r"(b[1]));
}

__device__ __forceinline__ void cp16(float* dst, const float* src, bool pred) {
    uint32_t d = (uint32_t)__cvta_generic_to_shared(dst);
    int sz = pred ? 16 : 0;
    asm volatile("cp.async.cg.shared.global [%0], [%1], 16, %2;"
                 :: "r"(d), "l"(src), "r"(sz));
}
__device__ __forceinline__ void cp_commit() {
    asm volatile("cp.async.commit_group;");
}
template<int N>
__device__ __forceinline__ void cp_wait() {
    asm volatile("cp.async.wait_group %0;" :: "n"(N));
}

// ---------------- tf32 GEMM: 64x128 CTA, 64x32 warp, BK=32, 2-stage ping-pong ----------------
// Barrier count halves vs BK=16; 4 CTAs/SM (53.25 KB smem), 128 threads.
#define BK   32
#define ASTR 36
#define BSTR 136
#define NSTG 2
#define GEMM_SMEM_BYTES ((NSTG * 64 * ASTR + NSTG * BK * BSTR) * 4)
__device__ __forceinline__ void gemm_core(
    const float* __restrict__ A, const float* __restrict__ W,
    const float* __restrict__ bias, float* __restrict__ C,
    int M, int N, int K, int do_relu, int do_round, int row0, int col0) {
    extern __shared__ float smg[];
    float* As = smg;                        // [NSTG][64][ASTR] (m,k)
    float* Bs = smg + NSTG * 64 * ASTR;     // [NSTG][BK][BSTR] (k,n)
    const int tid = threadIdx.x;
    const int wid = tid >> 5, lane = tid & 31;
    const int wn  = wid * 32;

    const int a_row = tid >> 1, a_k = (tid & 1) * 16;
    const int b_k   = tid >> 2, b_n = (tid & 3) * 32;
    const int a_grow = row0 + a_row;
    const bool a_ok = (a_grow < M);
    const float* a_src = A + (size_t)a_grow * K + a_k;
    const float* b_src = W + (size_t)b_k * N + col0 + b_n;

    auto load_stage = [&](int st, int k0) {
        float* ad = As + (st * 64 + a_row) * ASTR + a_k;
        #pragma unroll
        for (int j = 0; j < 4; j++)
            cp16(ad + 4*j, a_src + k0 + 4*j, a_ok);
        float* bd = Bs + (st * BK + b_k) * BSTR + b_n;
        const float* bs = b_src + (size_t)k0 * N;
        #pragma unroll
        for (int j = 0; j < 8; j++)
            cp16(bd + 4*j, bs + 4*j, true);
    };

    float acc[4][4][4];
    #pragma unroll
    for (int mt = 0; mt < 4; mt++)
        #pragma unroll
        for (int nt = 0; nt < 4; nt++)
            #pragma unroll
            for (int i = 0; i < 4; i++) acc[mt][nt][i] = 0.0f;

    load_stage(0, 0);
    cp_commit();

    const int r = lane >> 2, c = lane & 3;
    int stage = 0;
    for (int k0 = 0; k0 < K; k0 += BK) {
        cp_wait<0>();
        __syncthreads();
        int kn = k0 + BK;
        if (kn < K) load_stage(stage ^ 1, kn);
        cp_commit();
        #pragma unroll
        for (int ks = 0; ks < BK; ks += 8) {
            uint32_t af[4][4], bfr[4][2];
            #pragma unroll
            for (int mt = 0; mt < 4; mt++) {
                const float* ap = As + (stage * 64 + mt * 16) * ASTR + ks;
                af[mt][0] = __float_as_uint(ap[(r    ) * ASTR + c    ]);
                af[mt][1] = __float_as_uint(ap[(r + 8) * ASTR + c    ]);
                af[mt][2] = __float_as_uint(ap[(r    ) * ASTR + c + 4]);
                af[mt][3] = __float_as_uint(ap[(r + 8) * ASTR + c + 4]);
            }
            #pragma unroll
            for (int nt = 0; nt < 4; nt++) {
                const float* bp = Bs + (stage * BK + ks) * BSTR + wn + nt * 8 + r;
                bfr[nt][0] = __float_as_uint(bp[(c    ) * BSTR]);
                bfr[nt][1] = __float_as_uint(bp[(c + 4) * BSTR]);
            }
            #pragma unroll
            for (int mt = 0; mt < 4; mt++)
                #pragma unroll
                for (int nt = 0; nt < 4; nt++)
                    mma1688(acc[mt][nt], af[mt], bfr[nt]);
        }
        stage ^= 1;
    }

    #pragma unroll
    for (int mt = 0; mt < 4; mt++) {
        int rrow = row0 + mt * 16 + (lane >> 2);
        #pragma unroll
        for (int nt = 0; nt < 4; nt++) {
            int ccol = col0 + wn + nt * 8 + (lane & 3) * 2;
            float2 v0 = make_float2(acc[mt][nt][0], acc[mt][nt][1]);
            float2 v1 = make_float2(acc[mt][nt][2], acc[mt][nt][3]);
            if (bias) {
                float b0 = bias[ccol], b1 = bias[ccol + 1];
                v0.x += b0; v0.y += b1;
                v1.x += b0; v1.y += b1;
            }
            if (do_relu) {
                v0.x = fmaxf(v0.x, 0.f); v0.y = fmaxf(v0.y, 0.f);
                v1.x = fmaxf(v1.x, 0.f); v1.y = fmaxf(v1.y, 0.f);
            }
            if (do_round) {
                v0.x = f2tf(v0.x); v0.y = f2tf(v0.y);
                v1.x = f2tf(v1.x); v1.y = f2tf(v1.y);
            }
            if (rrow < M)     *(float2*)(C + (size_t)rrow     * N + ccol) = v0;
            if (rrow + 8 < M) *(float2*)(C + (size_t)(rrow+8) * N + ccol) = v1;
        }
    }
}

__global__ __launch_bounds__(128, 4) void mma_gemm_kernel(
    const float* __restrict__ A, const float* __restrict__ W,
    const float* __restrict__ bias, float* __restrict__ C,
    int M, int N, int K, int do_relu, int do_round) {
    gemm_core(A, W, bias, C, M, N, K, do_relu, do_round,
              blockIdx.y * 64, blockIdx.x * 128);
}

__global__ __launch_bounds__(128, 4) void qkv_gemm_kernel(
    const float* __restrict__ X,
    const float* __restrict__ Wq, const float* __restrict__ Wk,
    const float* __restrict__ Wv,
    float* __restrict__ Qo, float* __restrict__ Ko, float* __restrict__ Vo,
    int M) {
    const float* W = (blockIdx.z == 0) ? Wq : ((blockIdx.z == 1) ? Wk : Wv);
    float*       C = (blockIdx.z == 0) ? Qo : ((blockIdx.z == 1) ? Ko : Vo);
    gemm_core(X, W, nullptr, C, M, DM, DM, 0, 1, blockIdx.y * 64, blockIdx.x * 128);
}

// ---------------- MMA attention (flash-style, 64-q tiles, sl-bounded) ----------------
#define SKT 68
#define SVT 72
#define SPT 76
#define SQTS 68
#define ATTN_SMEM_FLOATS (64*SKT + 64*SVT + 4*16*SPT + 64)

__global__ __launch_bounds__(128, 4) void attn_mma_kernel(
    const float* __restrict__ Q, const float* __restrict__ K,
    const float* __restrict__ V, float* __restrict__ O, int L) {
    extern __shared__ float sm[];
    float* sK  = sm;
    float* sV  = sK + 64 * SKT;
    float* sPa = sV + 64 * SVT;
    float* sQT = sPa;
    float* sW  = sPa + 4 * 16 * SPT;

    int b = blockIdx.x, h = blockIdx.y, qt = blockIdx.z;
    int tid = threadIdx.x, w = tid >> 5, lane = tid & 31;
    int r = lane >> 2, c = lane & 3;
    int sl = g_seq_len[b];
    size_t base = ((size_t)b * L) * DM + h * DKH;
    int q0 = qt * 64;
    int qb = w * 16;
    float* sP = sPa + w * 16 * SPT;
    float* sWw = sW + w * 16;

    for (int idx = tid; idx < 64 * 16; idx += 128) {
        int qq = idx >> 4, dd = (idx & 15) * 4;
        int gq = q0 + qq; if (gq >= L) gq = L - 1;
        float4 qv = *(const float4*)(Q + base + (size_t)gq * DM + dd);
        sQT[(dd+0) * SQTS + qq] = qv.x;
        sQT[(dd+1) * SQTS + qq] = qv.y;
        sQT[(dd+2) * SQTS + qq] = qv.z;
        sQT[(dd+3) * SQTS + qq] = qv.w;
    }
    __syncthreads();
    uint32_t bq[8][2][2];
    #pragma unroll
    for (int k8 = 0; k8 < 8; k8++)
        #pragma unroll
        for (int nt = 0; nt < 2; nt++) {
            int qn = qb + nt * 8 + r;
            bq[k8][nt][0] = __float_as_uint(sQT[(k8*8 + c    ) * SQTS + qn]);
            bq[k8][nt][1] = __float_as_uint(sQT[(k8*8 + c + 4) * SQTS + qn]);
        }

    float oacc[8][4];
    #pragma unroll
    for (int d = 0; d < 8; d++)
        #pragma unroll
        for (int i = 0; i < 4; i++) oacc[d][i] = 0.0f;
    float mrow[2][2] = {{-3.0e38f, -3.0e38f}, {-3.0e38f, -3.0e38f}};
    float lrow[2][2] = {{0.f, 0.f}, {0.f, 0.f}};

    for (int j0 = 0; j0 < sl; j0 += 64) {
        __syncthreads();
        for (int idx = tid; idx < 64 * 16; idx += 128) {
            int kr = idx >> 4, dd = (idx & 15) * 4;
            int gj = j0 + kr;
            float4 kv = make_float4(0.f,0.f,0.f,0.f), vv = kv;
            if (gj < L) {
                kv = *(const float4*)(K + base + (size_t)gj * DM + dd);
                vv = *(const float4*)(V + base + (size_t)gj * DM + dd);
            }
            *(float4*)&sK[kr * SKT + dd] = kv;
            *(float4*)&sV[kr * SVT + dd] = vv;
        }
        __syncthreads();

        float sfr[4][2][4];
        #pragma unroll
        for (int mt = 0; mt < 4; mt++)
            #pragma unroll
            for (int nt = 0; nt < 2; nt++)
                #pragma unroll
                for (int i = 0; i < 4; i++) sfr[mt][nt][i] = 0.f;

        #pragma unroll
        for (int kk = 0; kk < 64; kk += 8) {
            #pragma unroll
            for (int mt = 0; mt < 4; mt++) {
                int mb = mt * 16;
                uint32_t a[4];
                a[0] = __float_as_uint(sK[(mb + r    ) * SKT + kk + c    ]);
                a[1] = __float_as_uint(sK[(mb + r + 8) * SKT + kk + c    ]);
                a[2] = __float_as_uint(sK[(mb + r    ) * SKT + kk + c + 4]);
                a[3] = __float_as_uint(sK[(mb + r + 8) * SKT + kk + c + 4]);
                #pragma unroll
                for (int nt = 0; nt < 2; nt++)
                    mma1688(sfr[mt][nt], a, bq[kk >> 3][nt]);
            }
        }

        float scl[2][2];
        #pragma unroll
        for (int nt = 0; nt < 2; nt++) {
            #pragma unroll
            for (int i = 0; i < 2; i++) {
                float cm = -3.0e38f;
                #pragma unroll
                for (int mt = 0; mt < 4; mt++) {
                    int j = j0 + mt * 16 + r;
                    float s0 = (j     < sl) ? sfr[mt][nt][i]   * 0.125f : -1e9f;
                    float s1 = (j + 8 < sl) ? sfr[mt][nt][2+i] * 0.125f : -1e9f;
                    sfr[mt][nt][i]   = s0;
                    sfr[mt][nt][2+i] = s1;
                    cm = fmaxf(cm, fmaxf(s0, s1));
                }
                cm = fmaxf(cm, __shfl_xor_sync(0xFFFFFFFFu, cm, 4));
                cm = fmaxf(cm, __shfl_xor_sync(0xFFFFFFFFu, cm, 8));
                cm = fmaxf(cm, __shfl_xor_sync(0xFFFFFFFFu, cm, 16));
                float mnew = fmaxf(mrow[nt][i], cm);
                float sc = expf(mrow[nt][i] - mnew);
                mrow[nt][i] = mnew;
                scl[nt][i] = sc;
                float ls = 0.f;
                #pragma unroll
                for (int mt = 0; mt < 4; mt++) {
                    float p0 = expf(sfr[mt][nt][i]   - mnew);
                    float p1 = expf(sfr[mt][nt][2+i] - mnew);
                    sfr[mt][nt][i]   = p0;
                    sfr[mt][nt][2+i] = p1;
                    ls += p0 + p1;
                }
                ls += __shfl_xor_sync(0xFFFFFFFFu, ls, 4);
                ls += __shfl_xor_sync(0xFFFFFFFFu, ls, 8);
                ls += __shfl_xor_sync(0xFFFFFFFFu, ls, 16);
                lrow[nt][i] = lrow[nt][i] * sc + ls;
            }
        }
        if (r == 0) {
            #pragma unroll
            for (int nt = 0; nt < 2; nt++)
                #pragma unroll
                for (int i = 0; i < 2; i++)
                    sWw[nt * 8 + 2 * c + i] = scl[nt][i];
        }
        __syncwarp();
        float rs0 = sWw[r], rs1 = sWw[r + 8];
        #pragma unroll
        for (int d = 0; d < 8; d++) {
            oacc[d][0] *= rs0; oacc[d][1] *= rs0;
            oacc[d][2] *= rs1; oacc[d][3] *= rs1;
        }
        #pragma unroll
        for (int nt = 0; nt < 2; nt++)
            #pragma unroll
            for (int i = 0; i < 2; i++) {
                int qq = nt * 8 + 2 * c + i;
                #pragma unroll
                for (int mt = 0; mt < 4; mt++) {
                    sP[qq * SPT + mt * 16 + r    ] = f2tf(sfr[mt][nt][i]);
                    sP[qq * SPT + mt * 16 + r + 8] = f2tf(sfr[mt][nt][2+i]);
                }
            }
        __syncwarp();
        #pragma unroll
        for (int kk = 0; kk < 64; kk += 8) {
            uint32_t a[4];
            a[0] = __float_as_uint(sP[(r    ) * SPT + kk + c    ]);
            a[1] = __float_as_uint(sP[(r + 8) * SPT + kk + c    ]);
            a[2] = __float_as_uint(sP[(r    ) * SPT + kk + c + 4]);
            a[3] = __float_as_uint(sP[(r + 8) * SPT + kk + c + 4]);
            #pragma unroll
            for (int dn = 0; dn < 8; dn++) {
                uint32_t bb2[2];
                bb2[0] = __float_as_uint(sV[(kk + c    ) * SVT + dn * 8 + r]);
                bb2[1] = __float_as_uint(sV[(kk + c + 4) * SVT + dn * 8 + r]);
                mma1688(oacc[dn], a, bb2);
            }
        }
    }

    if (r == 0) {
        #pragma unroll
        for (int nt = 0; nt < 2; nt++)
            #pragma unroll
            for (int i = 0; i < 2; i++)
                sWw[nt * 8 + 2 * c + i] = 1.0f / lrow[nt][i];
    }
    __syncwarp();
    float inv0 = sWw[r], inv1 = sWw[r + 8];
    int gq0 = q0 + qb + r, gq1 = gq0 + 8;
    #pragma unroll
    for (int dn = 0; dn < 8; dn++) {
        int col = dn * 8 + 2 * c;
        if (gq0 < L)
            *(float2*)(O + base + (size_t)gq0 * DM + col) =
                make_float2(f2tf(oacc[dn][0] * inv0), f2tf(oacc[dn][1] * inv0));
        if (gq1 < L)
            *(float2*)(O + base + (size_t)gq1 * DM + col) =
                make_float2(f2tf(oacc[dn][2] * inv1), f2tf(oacc[dn][3] * inv1));
    }
}

// ---------------- mask writeout ----------------
__global__ void mask_kernel(float* __restrict__ out, int L) {
    int idx = blockIdx.x * blockDim.x + threadIdx.x;
    if (idx < BB * L) {
        int b = idx / L, l = idx - b * L;
        out[(size_t)BB * L * DM + idx] = (l < g_seq_len[b]) ? 1.0f : 0.0f;
    }
}

// ---------------- host launcher ----------------
extern "C" void kernel_launch(void* const* d_in, const int* in_sizes, int n_in,
                              void* d_out, int out_size) {
    const int*   poi_type = (const int*)  d_in[0];
    const float* loc_emb  = (const float*)d_in[1];
    const int*   npl      = (const int*)  d_in[2];
    const int*   ttn      = (const int*)  d_in[3];
    const float* emb      = (const float*)d_in[4];
    const float* Wq       = (const float*)d_in[5];
    const float* Wk       = (const float*)d_in[6];
    const float* Wv       = (const float*)d_in[7];
    const float* Wo       = (const float*)d_in[8];
    const float* bo       = (const float*)d_in[9];
    const float* ln1_g    = (const float*)d_in[10];
    const float* ln1_b    = (const float*)d_in[11];
    const float* W1       = (const float*)d_in[12];
    const float* b1       = (const float*)d_in[13];
    const float* W2       = (const float*)d_in[14];
    const float* b2       = (const float*)d_in[15];
    const float* ln2_g    = (const float*)d_in[16];
    const float* ln2_b    = (const float*)d_in[17];
    const float* lnf_g    = (const float*)d_in[18];
    const float* lnf_b    = (const float*)d_in[19];

    int L, with_mask;
    if (out_size % (BB * (DM + 1)) == 0) { L = out_size / (BB * (DM + 1)); with_mask = 1; }
    else                                 { L = out_size / (BB * DM);        with_mask = 0; }
    const int M = BB * L;

    float *x, *q, *k, *v, *ao, *y, *hbuf;
    float *wqr, *wkr, *wvr, *wor, *w1r, *w2r;
    cudaGetSymbolAddress((void**)&x,    g_x);
    cudaGetSymbolAddress((void**)&q,    g_q);
    cudaGetSymbolAddress((void**)&k,    g_k);
    cudaGetSymbolAddress((void**)&v,    g_v);
    cudaGetSymbolAddress((void**)&ao,   g_ao);
    cudaGetSymbolAddress((void**)&y,    g_y);
    cudaGetSymbolAddress((void**)&hbuf, g_h);
    cudaGetSymbolAddress((void**)&wqr,  g_wq);
    cudaGetSymbolAddress((void**)&wkr,  g_wk);
    cudaGetSymbolAddress((void**)&wvr,  g_wv);
    cudaGetSymbolAddress((void**)&wor,  g_wo);
    cudaGetSymbolAddress((void**)&w1r,  g_w1);
    cudaGetSymbolAddress((void**)&w2r,  g_w2);

    int attn_smem = ATTN_SMEM_FLOATS * 4;
    cudaFuncSetAttribute(attn_mma_kernel,
                         cudaFuncAttributeMaxDynamicSharedMemorySize, attn_smem);
    cudaFuncSetAttribute(mma_gemm_kernel,
                         cudaFuncAttributeMaxDynamicSharedMemorySize, GEMM_SMEM_BYTES);
    cudaFuncSetAttribute(qkv_gemm_kernel,
                         cudaFuncAttributeMaxDynamicSharedMemorySize, GEMM_SMEM_BYTES);

    round_all_kernel<<<4096, 256>>>(
        (const float4*)Wq, (const float4*)Wk, (const float4*)Wv,
        (const float4*)Wo, (const float4*)W1, (const float4*)W2,
        (float4*)wqr, (float4*)wkr, (float4*)wvr,
        (float4*)wor, (float4*)w1r, (float4*)w2r);
    postab_kernel<<<SS, 128>>>();

    pack_kernel<<<1, 64>>>(npl, ttn, L);
    embed_ln_kernel<<<M, 128>>>(poi_type, loc_emb, emb, lnf_g, lnf_b, L);

    int my = (M + 63) / 64;
    int nq = (L + 63) / 64;
    int ln_grid = (M + 7) / 8;
    dim3 g512(4, my);
    dim3 g2048(16, my);
    dim3 gqkv(4, my, 3);
    dim3 gattn(BB, NH, nq);

    for (int l = 0; l < NLAY; l++) {
        const float* wq = wqr + (size_t)l * DM * DM;
        const float* wk = wkr + (size_t)l * DM * DM;
        const float* wv = wvr + (size_t)l * DM * DM;
        const float* wo = wor + (size_t)l * DM * DM;
        const float* w1 = w1r + (size_t)l * DM * DI;
        const float* w2 = w2r + (size_t)l * DI * DM;

        qkv_gemm_kernel<<<gqkv, 128, GEMM_SMEM_BYTES>>>(x, wq, wk, wv, q, k, v, M);
        attn_mma_kernel<<<gattn, 128, attn_smem>>>(q, k, v, ao, L);
        mma_gemm_kernel<<<g512, 128, GEMM_SMEM_BYTES>>>(ao, wo, bo + (size_t)l * DM, y, M, DM, DM, 0, 0);
        resid_ln_kernel<<<ln_grid, 256>>>(x, y, ln1_g + (size_t)l * DM, ln1_b + (size_t)l * DM, x, 1, M);
        mma_gemm_kernel<<<g2048, 128, GEMM_SMEM_BYTES>>>(x, w1, b1 + (size_t)l * DI, hbuf, M, DI, DM, 1, 1);
        mma_gemm_kernel<<<g512, 128, GEMM_SMEM_BYTES>>>(hbuf, w2, b2 + (size_t)l * DM, y, M, DM, DI, 0, 0);
        float* dst = (l == NLAY - 1) ? (float*)d_out : x;
        int rnd = (l == NLAY - 1) ? 0 : 1;
        resid_ln_kernel<<<ln_grid, 256>>>(x, y, ln2_g + (size_t)l * DM, ln2_b + (size_t)l * DM, dst, rnd, M);
    }

    if (with_mask)
        mask_kernel<<<(BB * L + 255) / 256, 256>>>((float*)d_out, L);
}

// round 16
// speedup vs baseline: 1.5784x; 1.5784x over previous
#include <cuda_runtime.h>
#include <math.h>
#include <stdint.h>

// ---------------- problem constants ----------------
#define BB   64
#define DM   512
#define NH   8
#define DKH  64
#define DI   2048
#define NLAY 4
#define SS   12
#define REP_IDX 1
#define LMAX 385

// ---------------- scratch ----------------
__device__ int   g_seq_len[BB];
__device__ int   g_poi_idx[BB * LMAX];
__device__ int   g_tok_idx[BB * LMAX];
__device__ float g_x [BB * LMAX * DM];
__device__ float g_q [BB * LMAX * DM];
__device__ float g_k [BB * LMAX * DM];
__device__ float g_v [BB * LMAX * DM];
__device__ float g_ao[BB * LMAX * DM];
__device__ float g_y [BB * LMAX * DM];
__device__ float g_h [BB * LMAX * DI];
__device__ float g_pt[SS * DM];
// tf32-rounded weights
__device__ float g_wq[NLAY * DM * DM];
__device__ float g_wk[NLAY * DM * DM];
__device__ float g_wv[NLAY * DM * DM];
__device__ float g_wo[NLAY * DM * DM];
__device__ float g_w1[NLAY * DM * DI];
__device__ float g_w2[NLAY * DI * DM];

// ---------------- tf32 helpers ----------------
__device__ __forceinline__ float f2tf(float x) {
    uint32_t u;
    asm("cvt.rna.tf32.f32 %0, %1;" : "=r"(u) : "f"(x));
    return __uint_as_float(u);
}
__device__ __forceinline__ float4 f2tf4(float4 a) {
    return make_float4(f2tf(a.x), f2tf(a.y), f2tf(a.z), f2tf(a.w));
}

// ---------------- fused weight rounding ----------------
#define NA (NLAY * DM * DM / 4)
#define NB (NLAY * DM * DI / 4)
__global__ void round_all_kernel(
    const float4* __restrict__ wq, const float4* __restrict__ wk,
    const float4* __restrict__ wv, const float4* __restrict__ wo,
    const float4* __restrict__ w1, const float4* __restrict__ w2,
    float4* __restrict__ dq, float4* __restrict__ dk,
    float4* __restrict__ dv, float4* __restrict__ doo,
    float4* __restrict__ d1, float4* __restrict__ d2) {
    const int total = 4 * NA + 2 * NB;
    int stride = gridDim.x * blockDim.x;
    for (int i = blockIdx.x * blockDim.x + threadIdx.x; i < total; i += stride) {
        const float4* s; float4* d; int off;
        if      (i <     NA)      { s = wq; d = dq;  off = i; }
        else if (i < 2 * NA)      { s = wk; d = dk;  off = i - NA; }
        else if (i < 3 * NA)      { s = wv; d = dv;  off = i - 2 * NA; }
        else if (i < 4 * NA)      { s = wo; d = doo; off = i - 3 * NA; }
        else if (i < 4 * NA + NB) { s = w1; d = d1;  off = i - 4 * NA; }
        else                      { s = w2; d = d2;  off = i - 4 * NA - NB; }
        d[off] = f2tf4(s[off]);
    }
}

// ---------------- sinusoid table ----------------
__global__ void postab_kernel() {
    int t = blockIdx.x;
    for (int d = threadIdx.x; d < DM; d += blockDim.x) {
        int i2 = d & ~1;
        float f = powf(10000.0f, -(float)i2 / (float)DM);
        float ang = (float)t * f;
        g_pt[t * DM + d] = (d & 1) ? cosf(ang) : sinf(ang);
    }
}

// ---------------- pack ----------------
__global__ void pack_kernel(const int* __restrict__ npl,
                            const int* __restrict__ ttn, int L) {
    int b = threadIdx.x;
    if (b >= BB) return;
    int start = 0;
    for (int i = 0; i < b; i++) start += npl[i];
    int end = start + npl[b];
    int pos = 1;
    for (int p = start; p < end; p++) {
        int t = ttn[p];
        for (int u = 0; u < t && pos < L; u++) {
            g_poi_idx[b * L + pos] = p;
            g_tok_idx[b * L + pos] = u;
            pos++;
        }
    }
    g_seq_len[b] = pos;
}

// ---------------- block reduce (128 threads) ----------------
__device__ __forceinline__ void block_reduce2_128(float& s, float& sq) {
    #pragma unroll
    for (int o = 16; o > 0; o >>= 1) {
        s  += __shfl_xor_sync(0xFFFFFFFFu, s,  o);
        sq += __shfl_xor_sync(0xFFFFFFFFu, sq, o);
    }
    __shared__ float rs[4], rq[4];
    int w = threadIdx.x >> 5, ln = threadIdx.x & 31;
    if (ln == 0) { rs[w] = s; rq[w] = sq; }
    __syncthreads();
    s  = rs[0] + rs[1] + rs[2] + rs[3];
    sq = rq[0] + rq[1] + rq[2] + rq[3];
}

// ---------------- embed + final LN ----------------
__global__ __launch_bounds__(128) void embed_ln_kernel(
    const int* __restrict__ poi_type, const float* __restrict__ loc_emb,
    const float* __restrict__ emb, const float* __restrict__ lnf_g,
    const float* __restrict__ lnf_b, int L) {
    int row = blockIdx.x;
    int b = row / L, l = row - b * L;
    int tid = threadIdx.x;
    int d0 = tid * 4;
    float v[4];
    int sl = g_seq_len[b];
    if (l == 0) {
        #pragma unroll
        for (int i = 0; i < 4; i++) v[i] = emb[REP_IDX * DM + d0 + i];
    } else if (l < sl) {
        int p = g_poi_idx[b * L + l];
        int t = g_tok_idx[b * L + l];
        int tok = poi_type[p * SS + t];
        float4 ev = *(const float4*)(emb + (size_t)tok * DM + d0);
        float4 pv = *(const float4*)(g_pt + t * DM + d0);
        float4 lv = *(const float4*)(loc_emb + (size_t)p * DM + d0);
        v[0] = ev.x + pv.x + lv.x;
        v[1] = ev.y + pv.y + lv.y;
        v[2] = ev.z + pv.z + lv.z;
        v[3] = ev.w + pv.w + lv.w;
    } else {
        #pragma unroll
        for (int i = 0; i < 4; i++) v[i] = 0.0f;
    }
    float s = v[0] + v[1] + v[2] + v[3];
    float sq = v[0]*v[0] + v[1]*v[1] + v[2]*v[2] + v[3]*v[3];
    block_reduce2_128(s, sq);
    float mean = s * (1.0f / DM);
    float var  = sq * (1.0f / DM) - mean * mean;
    float r = rsqrtf(var + 1e-6f);
    float4 o;
    o.x = f2tf(lnf_g[d0+0] * (v[0]-mean) * r + lnf_b[d0+0]);
    o.y = f2tf(lnf_g[d0+1] * (v[1]-mean) * r + lnf_b[d0+1]);
    o.z = f2tf(lnf_g[d0+2] * (v[2]-mean) * r + lnf_b[d0+2]);
    o.w = f2tf(lnf_g[d0+3] * (v[3]-mean) * r + lnf_b[d0+3]);
    *(float4*)(g_x + (size_t)row * DM + d0) = o;
}

// ---------------- residual + LN: warp per row ----------------
__global__ __launch_bounds__(256) void resid_ln_kernel(
    const float* __restrict__ x, const float* __restrict__ y,
    const float* __restrict__ g, const float* __restrict__ bb,
    float* __restrict__ dst, int do_round, int M) {
    int row = blockIdx.x * 8 + (threadIdx.x >> 5);
    if (row >= M) return;
    int lane = threadIdx.x & 31;
    size_t base = (size_t)row * DM + lane * 4;
    float4 a[4];
    float s = 0.f, sq = 0.f;
    #pragma unroll
    for (int j = 0; j < 4; j++) {
        float4 xv = *(const float4*)(x + base + j * 128);
        float4 yv = *(const float4*)(y + base + j * 128);
        float4 t = make_float4(xv.x+yv.x, xv.y+yv.y, xv.z+yv.z, xv.w+yv.w);
        a[j] = t;
        s  += t.x + t.y + t.z + t.w;
        sq += t.x*t.x + t.y*t.y + t.z*t.z + t.w*t.w;
    }
    #pragma unroll
    for (int o = 16; o > 0; o >>= 1) {
        s  += __shfl_xor_sync(0xFFFFFFFFu, s,  o);
        sq += __shfl_xor_sync(0xFFFFFFFFu, sq, o);
    }
    float mean = s * (1.0f / DM);
    float var  = sq * (1.0f / DM) - mean * mean;
    float r = rsqrtf(var + 1e-6f);
    #pragma unroll
    for (int j = 0; j < 4; j++) {
        int d0 = lane * 4 + j * 128;
        float4 o;
        o.x = g[d0+0] * (a[j].x - mean) * r + bb[d0+0];
        o.y = g[d0+1] * (a[j].y - mean) * r + bb[d0+1];
        o.z = g[d0+2] * (a[j].z - mean) * r + bb[d0+2];
        o.w = g[d0+3] * (a[j].w - mean) * r + bb[d0+3];
        if (do_round) o = f2tf4(o);
        *(float4*)(dst + base + j * 128) = o;
    }
}

// ---------------- mma helper ----------------
__device__ __forceinline__ void mma1688(float* c, const uint32_t* a, const uint32_t* b) {
    asm volatile(
        "mma.sync.aligned.m16n8k8.row.col.f32.tf32.tf32.f32 "
        "{%0,%1,%2,%3}, {%4,%5,%6,%7}, {%8,%9}, {%0,%1,%2,%3};"
        : "+f"(c[0]), "+f"(c[1]), "+f"(c[2]), "+f"(c[3])
        : "r"(a[0]), "r"(a[1]), "r"(a[2]), "r"(a[3]),
          "r"(b[0]), "r"(b[1]));
}

__device__ __forceinline__ void cp16(float* dst, const float* src, bool pred) {
    uint32_t d = (uint32_t)__cvta_generic_to_shared(dst);
    int sz = pred ? 16 : 0;
    asm volatile("cp.async.cg.shared.global [%0], [%1], 16, %2;"
                 :: "r"(d), "l"(src), "r"(sz));
}
__device__ __forceinline__ void cp_commit() {
    asm volatile("cp.async.commit_group;");
}
template<int N>
__device__ __forceinline__ void cp_wait() {
    asm volatile("cp.async.wait_group %0;" :: "n"(N));
}

// ---------------- tf32 GEMM: 64x128 CTA, 64x32 warp, 4 CTA/SM, 4-stage (R13 config) ----------------
#define BK   16
#define ASTR 20
#define BSTR 136
#define NSTG 4
#define GEMM_SMEM_BYTES ((NSTG * 64 * ASTR + NSTG * BK * BSTR) * 4)
__device__ __forceinline__ void gemm_core(
    const float* __restrict__ A, const float* __restrict__ W,
    const float* __restrict__ bias, float* __restrict__ C,
    int M, int N, int K, int do_relu, int do_round, int row0, int col0) {
    extern __shared__ float smg[];
    float* As = smg;                       // [NSTG][64][ASTR]  (m,k)
    float* Bs = smg + NSTG * 64 * ASTR;    // [NSTG][BK][BSTR]  (k,n)
    const int tid = threadIdx.x;
    const int wid = tid >> 5, lane = tid & 31;
    const int wn  = wid * 32;

    const int a_row = tid >> 1, a_k = (tid & 1) * 8;
    const int b_k   = tid >> 5, b_n = (tid & 31) * 4;
    const int a_grow = row0 + a_row;
    const bool a_ok = (a_grow < M);
    const float* a_src = A + (size_t)a_grow * K + a_k;
    const float* b_src = W + (size_t)b_k * N + col0 + b_n;

    auto load_stage = [&](int st, int k0) {
        float* ad = As + (st * 64 + a_row) * ASTR + a_k;
        cp16(ad,     a_src + k0,     a_ok);
        cp16(ad + 4, a_src + k0 + 4, a_ok);
        #pragma unroll
        for (int j = 0; j < 4; j++)
            cp16(Bs + (st * BK + b_k + 4*j) * BSTR + b_n,
                 b_src + (size_t)(k0 + 4*j) * N, true);
    };

    float acc[4][4][4];
    #pragma unroll
    for (int mt = 0; mt < 4; mt++)
        #pragma unroll
        for (int nt = 0; nt < 4; nt++)
            #pragma unroll
            for (int i = 0; i < 4; i++) acc[mt][nt][i] = 0.0f;

    #pragma unroll
    for (int s = 0; s < NSTG - 1; s++) {
        load_stage(s, s * BK);
        cp_commit();
    }

    const int r = lane >> 2, c = lane & 3;
    int stage = 0;
    for (int k0 = 0; k0 < K; k0 += BK) {
        cp_wait<NSTG - 2>();
        __syncthreads();
        int kn = k0 + (NSTG - 1) * BK;
        if (kn < K) load_stage((stage + NSTG - 1) % NSTG, kn);
        cp_commit();
        #pragma unroll
        for (int ks = 0; ks < BK; ks += 8) {
            uint32_t af[4][4], bfr[4][2];
            #pragma unroll
            for (int mt = 0; mt < 4; mt++) {
                const float* ap = As + (stage * 64 + mt * 16) * ASTR + ks;
                af[mt][0] = __float_as_uint(ap[(r    ) * ASTR + c    ]);
                af[mt][1] = __float_as_uint(ap[(r + 8) * ASTR + c    ]);
                af[mt][2] = __float_as_uint(ap[(r    ) * ASTR + c + 4]);
                af[mt][3] = __float_as_uint(ap[(r + 8) * ASTR + c + 4]);
            }
            #pragma unroll
            for (int nt = 0; nt < 4; nt++) {
                const float* bp = Bs + (stage * BK + ks) * BSTR + wn + nt * 8 + r;
                bfr[nt][0] = __float_as_uint(bp[(c    ) * BSTR]);
                bfr[nt][1] = __float_as_uint(bp[(c + 4) * BSTR]);
            }
            #pragma unroll
            for (int mt = 0; mt < 4; mt++)
                #pragma unroll
                for (int nt = 0; nt < 4; nt++)
                    mma1688(acc[mt][nt], af[mt], bfr[nt]);
        }
        stage = (stage + 1) % NSTG;
    }

    #pragma unroll
    for (int mt = 0; mt < 4; mt++) {
        int rrow = row0 + mt * 16 + (lane >> 2);
        #pragma unroll
        for (int nt = 0; nt < 4; nt++) {
            int ccol = col0 + wn + nt * 8 + (lane & 3) * 2;
            float2 v0 = make_float2(acc[mt][nt][0], acc[mt][nt][1]);
            float2 v1 = make_float2(acc[mt][nt][2], acc[mt][nt][3]);
            if (bias) {
                float b0 = bias[ccol], b1 = bias[ccol + 1];
                v0.x += b0; v0.y += b1;
                v1.x += b0; v1.y += b1;
            }
            if (do_relu) {
                v0.x = fmaxf(v0.x, 0.f); v0.y = fmaxf(v0.y, 0.f);
                v1.x = fmaxf(v1.x, 0.f); v1.y = fmaxf(v1.y, 0.f);
            }
            if (do_round) {
                v0.x = f2tf(v0.x); v0.y = f2tf(v0.y);
                v1.x = f2tf(v1.x); v1.y = f2tf(v1.y);
            }
            if (rrow < M)     *(float2*)(C + (size_t)rrow     * N + ccol) = v0;
            if (rrow + 8 < M) *(float2*)(C + (size_t)(rrow+8) * N + ccol) = v1;
        }
    }
}

__global__ __launch_bounds__(128, 4) void mma_gemm_kernel(
    const float* __restrict__ A, const float* __restrict__ W,
    const float* __restrict__ bias, float* __restrict__ C,
    int M, int N, int K, int do_relu, int do_round) {
    gemm_core(A, W, bias, C, M, N, K, do_relu, do_round,
              blockIdx.y * 64, blockIdx.x * 128);
}

__global__ __launch_bounds__(128, 4) void qkv_gemm_kernel(
    const float* __restrict__ X,
    const float* __restrict__ Wq, const float* __restrict__ Wk,
    const float* __restrict__ Wv,
    float* __restrict__ Qo, float* __restrict__ Ko, float* __restrict__ Vo,
    int M) {
    const float* W = (blockIdx.z == 0) ? Wq : ((blockIdx.z == 1) ? Wk : Wv);
    float*       C = (blockIdx.z == 0) ? Qo : ((blockIdx.z == 1) ? Ko : Vo);
    gemm_core(X, W, nullptr, C, M, DM, DM, 0, 1, blockIdx.y * 64, blockIdx.x * 128);
}

// ---------------- MMA attention (flash-style, 64-q tiles, sl-bounded key loop) ----------------
#define SKT 68
#define SVT 72
#define SPT 76
#define SQTS 68
#define ATTN_SMEM_FLOATS (64*SKT + 64*SVT + 4*16*SPT + 64)

__global__ __launch_bounds__(128, 4) void attn_mma_kernel(
    const float* __restrict__ Q, const float* __restrict__ K,
    const float* __restrict__ V, float* __restrict__ O, int L) {
    extern __shared__ float sm[];
    float* sK  = sm;
    float* sV  = sK + 64 * SKT;
    float* sPa = sV + 64 * SVT;
    float* sQT = sPa;
    float* sW  = sPa + 4 * 16 * SPT;

    int b = blockIdx.x, h = blockIdx.y, qt = blockIdx.z;
    int tid = threadIdx.x, w = tid >> 5, lane = tid & 31;
    int r = lane >> 2, c = lane & 3;
    int sl = g_seq_len[b];
    size_t base = ((size_t)b * L) * DM + h * DKH;
    int q0 = qt * 64;
    int qb = w * 16;
    float* sP = sPa + w * 16 * SPT;
    float* sWw = sW + w * 16;

    for (int idx = tid; idx < 64 * 16; idx += 128) {
        int qq = idx >> 4, dd = (idx & 15) * 4;
        int gq = q0 + qq; if (gq >= L) gq = L - 1;
        float4 qv = *(const float4*)(Q + base + (size_t)gq * DM + dd);
        sQT[(dd+0) * SQTS + qq] = qv.x;
        sQT[(dd+1) * SQTS + qq] = qv.y;
        sQT[(dd+2) * SQTS + qq] = qv.z;
        sQT[(dd+3) * SQTS + qq] = qv.w;
    }
    __syncthreads();
    uint32_t bq[8][2][2];
    #pragma unroll
    for (int k8 = 0; k8 < 8; k8++)
        #pragma unroll
        for (int nt = 0; nt < 2; nt++) {
            int qn = qb + nt * 8 + r;
            bq[k8][nt][0] = __float_as_uint(sQT[(k8*8 + c    ) * SQTS + qn]);
            bq[k8][nt][1] = __float_as_uint(sQT[(k8*8 + c + 4) * SQTS + qn]);
        }

    float oacc[8][4];
    #pragma unroll
    for (int d = 0; d < 8; d++)
        #pragma unroll
        for (int i = 0; i < 4; i++) oacc[d][i] = 0.0f;
    float mrow[2][2] = {{-3.0e38f, -3.0e38f}, {-3.0e38f, -3.0e38f}};
    float lrow[2][2] = {{0.f, 0.f}, {0.f, 0.f}};

    // keys >= sl contribute exactly 0 (exp underflow vs finite row max):
    // bounding by sl is bit-identical and skips ~16% of chunks on average.
    for (int j0 = 0; j0 < sl; j0 += 64) {
        __syncthreads();
        for (int idx = tid; idx < 64 * 16; idx += 128) {
            int kr = idx >> 4, dd = (idx & 15) * 4;
            int gj = j0 + kr;
            float4 kv = make_float4(0.f,0.f,0.f,0.f), vv = kv;
            if (gj < L) {
                kv = *(const float4*)(K + base + (size_t)gj * DM + dd);
                vv = *(const float4*)(V + base + (size_t)gj * DM + dd);
            }
            *(float4*)&sK[kr * SKT + dd] = kv;
            *(float4*)&sV[kr * SVT + dd] = vv;
        }
        __syncthreads();

        float sfr[4][2][4];
        #pragma unroll
        for (int mt = 0; mt < 4; mt++)
            #pragma unroll
            for (int nt = 0; nt < 2; nt++)
                #pragma unroll
                for (int i = 0; i < 4; i++) sfr[mt][nt][i] = 0.f;

        #pragma unroll
        for (int kk = 0; kk < 64; kk += 8) {
            #pragma unroll
            for (int mt = 0; mt < 4; mt++) {
                int mb = mt * 16;
                uint32_t a[4];
                a[0] = __float_as_uint(sK[(mb + r    ) * SKT + kk + c    ]);
                a[1] = __float_as_uint(sK[(mb + r + 8) * SKT + kk + c    ]);
                a[2] = __float_as_uint(sK[(mb + r    ) * SKT + kk + c + 4]);
                a[3] = __float_as_uint(sK[(mb + r + 8) * SKT + kk + c + 4]);
                #pragma unroll
                for (int nt = 0; nt < 2; nt++)
                    mma1688(sfr[mt][nt], a, bq[kk >> 3][nt]);
            }
        }

        float scl[2][2];
        #pragma unroll
        for (int nt = 0; nt < 2; nt++) {
            #pragma unroll
            for (int i = 0; i < 2; i++) {
                float cm = -3.0e38f;
                #pragma unroll
                for (int mt = 0; mt < 4; mt++) {
                    int j = j0 + mt * 16 + r;
                    float s0 = (j     < sl) ? sfr[mt][nt][i]   * 0.125f : -1e9f;
                    float s1 = (j + 8 < sl) ? sfr[mt][nt][2+i] * 0.125f : -1e9f;
                    sfr[mt][nt][i]   = s0;
                    sfr[mt][nt][2+i] = s1;
                    cm = fmaxf(cm, fmaxf(s0, s1));
                }
                cm = fmaxf(cm, __shfl_xor_sync(0xFFFFFFFFu, cm, 4));
                cm = fmaxf(cm, __shfl_xor_sync(0xFFFFFFFFu, cm, 8));
                cm = fmaxf(cm, __shfl_xor_sync(0xFFFFFFFFu, cm, 16));
                float mnew = fmaxf(mrow[nt][i], cm);
                float sc = expf(mrow[nt][i] - mnew);
                mrow[nt][i] = mnew;
                scl[nt][i] = sc;
                float ls = 0.f;
                #pragma unroll
                for (int mt = 0; mt < 4; mt++) {
                    float p0 = expf(sfr[mt][nt][i]   - mnew);
                    float p1 = expf(sfr[mt][nt][2+i] - mnew);
                    sfr[mt][nt][i]   = p0;
                    sfr[mt][nt][2+i] = p1;
                    ls += p0 + p1;
                }
                ls += __shfl_xor_sync(0xFFFFFFFFu, ls, 4);
                ls += __shfl_xor_sync(0xFFFFFFFFu, ls, 8);
                ls += __shfl_xor_sync(0xFFFFFFFFu, ls, 16);
                lrow[nt][i] = lrow[nt][i] * sc + ls;
            }
        }
        if (r == 0) {
            #pragma unroll
            for (int nt = 0; nt < 2; nt++)
                #pragma unroll
                for (int i = 0; i < 2; i++)
                    sWw[nt * 8 + 2 * c + i] = scl[nt][i];
        }
        __syncwarp();
        float rs0 = sWw[r], rs1 = sWw[r + 8];
        #pragma unroll
        for (int d = 0; d < 8; d++) {
            oacc[d][0] *= rs0; oacc[d][1] *= rs0;
            oacc[d][2] *= rs1; oacc[d][3] *= rs1;
        }
        #pragma unroll
        for (int nt = 0; nt < 2; nt++)
            #pragma unroll
            for (int i = 0; i < 2; i++) {
                int qq = nt * 8 + 2 * c + i;
                #pragma unroll
                for (int mt = 0; mt < 4; mt++) {
                    sP[qq * SPT + mt * 16 + r    ] = f2tf(sfr[mt][nt][i]);
                    sP[qq * SPT + mt * 16 + r + 8] = f2tf(sfr[mt][nt][2+i]);
                }
            }
        __syncwarp();
        #pragma unroll
        for (int kk = 0; kk < 64; kk += 8) {
            uint32_t a[4];
            a[0] = __float_as_uint(sP[(r    ) * SPT + kk + c    ]);
            a[1] = __float_as_uint(sP[(r + 8) * SPT + kk + c    ]);
            a[2] = __float_as_uint(sP[(r    ) * SPT + kk + c + 4]);
            a[3] = __float_as_uint(sP[(r + 8) * SPT + kk + c + 4]);
            #pragma unroll
            for (int dn = 0; dn < 8; dn++) {
                uint32_t bb2[2];
                bb2[0] = __float_as_uint(sV[(kk + c    ) * SVT + dn * 8 + r]);
                bb2[1] = __float_as_uint(sV[(kk + c + 4) * SVT + dn * 8 + r]);
                mma1688(oacc[dn], a, bb2);
            }
        }
    }

    if (r == 0) {
        #pragma unroll
        for (int nt = 0; nt < 2; nt++)
            #pragma unroll
            for (int i = 0; i < 2; i++)
                sWw[nt * 8 + 2 * c + i] = 1.0f / lrow[nt][i];
    }
    __syncwarp();
    float inv0 = sWw[r], inv1 = sWw[r + 8];
    int gq0 = q0 + qb + r, gq1 = gq0 + 8;
    #pragma unroll
    for (int dn = 0; dn < 8; dn++) {
        int col = dn * 8 + 2 * c;
        if (gq0 < L)
            *(float2*)(O + base + (size_t)gq0 * DM + col) =
                make_float2(f2tf(oacc[dn][0] * inv0), f2tf(oacc[dn][1] * inv0));
        if (gq1 < L)
            *(float2*)(O + base + (size_t)gq1 * DM + col) =
                make_float2(f2tf(oacc[dn][2] * inv1), f2tf(oacc[dn][3] * inv1));
    }
}

// ---------------- mask writeout ----------------
__global__ void mask_kernel(float* __restrict__ out, int L) {
    int idx = blockIdx.x * blockDim.x + threadIdx.x;
    if (idx < BB * L) {
        int b = idx / L, l = idx - b * L;
        out[(size_t)BB * L * DM + idx] = (l < g_seq_len[b]) ? 1.0f : 0.0f;
    }
}

// ---------------- host launcher ----------------
extern "C" void kernel_launch(void* const* d_in, const int* in_sizes, int n_in,
                              void* d_out, int out_size) {
    const int*   poi_type = (const int*)  d_in[0];
    const float* loc_emb  = (const float*)d_in[1];
    const int*   npl      = (const int*)  d_in[2];
    const int*   ttn      = (const int*)  d_in[3];
    const float* emb      = (const float*)d_in[4];
    const float* Wq       = (const float*)d_in[5];
    const float* Wk       = (const float*)d_in[6];
    const float* Wv       = (const float*)d_in[7];
    const float* Wo       = (const float*)d_in[8];
    const float* bo       = (const float*)d_in[9];
    const float* ln1_g    = (const float*)d_in[10];
    const float* ln1_b    = (const float*)d_in[11];
    const float* W1       = (const float*)d_in[12];
    const float* b1       = (const float*)d_in[13];
    const float* W2       = (const float*)d_in[14];
    const float* b2       = (const float*)d_in[15];
    const float* ln2_g    = (const float*)d_in[16];
    const float* ln2_b    = (const float*)d_in[17];
    const float* lnf_g    = (const float*)d_in[18];
    const float* lnf_b    = (const float*)d_in[19];

    int L, with_mask;
    if (out_size % (BB * (DM + 1)) == 0) { L = out_size / (BB * (DM + 1)); with_mask = 1; }
    else                                 { L = out_size / (BB * DM);        with_mask = 0; }
    const int M = BB * L;

    float *x, *q, *k, *v, *ao, *y, *hbuf;
    float *wqr, *wkr, *wvr, *wor, *w1r, *w2r;
    cudaGetSymbolAddress((void**)&x,    g_x);
    cudaGetSymbolAddress((void**)&q,    g_q);
    cudaGetSymbolAddress((void**)&k,    g_k);
    cudaGetSymbolAddress((void**)&v,    g_v);
    cudaGetSymbolAddress((void**)&ao,   g_ao);
    cudaGetSymbolAddress((void**)&y,    g_y);
    cudaGetSymbolAddress((void**)&hbuf, g_h);
    cudaGetSymbolAddress((void**)&wqr,  g_wq);
    cudaGetSymbolAddress((void**)&wkr,  g_wk);
    cudaGetSymbolAddress((void**)&wvr,  g_wv);
    cudaGetSymbolAddress((void**)&wor,  g_wo);
    cudaGetSymbolAddress((void**)&w1r,  g_w1);
    cudaGetSymbolAddress((void**)&w2r,  g_w2);

    int attn_smem = ATTN_SMEM_FLOATS * 4;
    cudaFuncSetAttribute(attn_mma_kernel,
                         cudaFuncAttributeMaxDynamicSharedMemorySize, attn_smem);
    cudaFuncSetAttribute(mma_gemm_kernel,
                         cudaFuncAttributeMaxDynamicSharedMemorySize, GEMM_SMEM_BYTES);
    cudaFuncSetAttribute(qkv_gemm_kernel,
                         cudaFuncAttributeMaxDynamicSharedMemorySize, GEMM_SMEM_BYTES);

    round_all_kernel<<<4096, 256>>>(
        (const float4*)Wq, (const float4*)Wk, (const float4*)Wv,
        (const float4*)Wo, (const float4*)W1, (const float4*)W2,
        (float4*)wqr, (float4*)wkr, (float4*)wvr,
        (float4*)wor, (float4*)w1r, (float4*)w2r);
    postab_kernel<<<SS, 128>>>();

    pack_kernel<<<1, 64>>>(npl, ttn, L);
    embed_ln_kernel<<<M, 128>>>(poi_type, loc_emb, emb, lnf_g, lnf_b, L);

    int my = (M + 63) / 64;
    int nq = (L + 63) / 64;
    int ln_grid = (M + 7) / 8;
    dim3 g512(4, my);
    dim3 g2048(16, my);
    dim3 gqkv(4, my, 3);
    dim3 gattn(BB, NH, nq);

    for (int l = 0; l < NLAY; l++) {
        const float* wq = wqr + (size_t)l * DM * DM;
        const float* wk = wkr + (size_t)l * DM * DM;
        const float* wv = wvr + (size_t)l * DM * DM;
        const float* wo = wor + (size_t)l * DM * DM;
        const float* w1 = w1r + (size_t)l * DM * DI;
        const float* w2 = w2r + (size_t)l * DI * DM;

        qkv_gemm_kernel<<<gqkv, 128, GEMM_SMEM_BYTES>>>(x, wq, wk, wv, q, k, v, M);
        attn_mma_kernel<<<gattn, 128, attn_smem>>>(q, k, v, ao, L);
        mma_gemm_kernel<<<g512, 128, GEMM_SMEM_BYTES>>>(ao, wo, bo + (size_t)l * DM, y, M, DM, DM, 0, 0);
        resid_ln_kernel<<<ln_grid, 256>>>(x, y, ln1_g + (size_t)l * DM, ln1_b + (size_t)l * DM, x, 1, M);
        mma_gemm_kernel<<<g2048, 128, GEMM_SMEM_BYTES>>>(x, w1, b1 + (size_t)l * DI, hbuf, M, DI, DM, 1, 1);
        mma_gemm_kernel<<<g512, 128, GEMM_SMEM_BYTES>>>(hbuf, w2, b2 + (size_t)l * DM, y, M, DM, DI, 0, 0);
        float* dst = (l == NLAY - 1) ? (float*)d_out : x;
        int rnd = (l == NLAY - 1) ? 0 : 1;
        resid_ln_kernel<<<ln_grid, 256>>>(x, y, ln2_g + (size_t)l * DM, ln2_b + (size_t)l * DM, dst, rnd, M);
    }

    if (with_mask)
        mask_kernel<<<(BB * L + 255) / 256, 256>>>((float*)d_out, L);
}